// round 7
// baseline (speedup 1.0000x reference)
#include <cuda_runtime.h>

#define NB    16384
#define SN    81
#define SS    (SN * SN)          // 6561
#define TOT   (NB * SS)          // 107,495,424
#define MAXLINE (TOT / 32 - 1)   // last valid 128B line index
#define HID   32
#define OBSW  162
#define BPB   8
#define NTHREADS (BPB * 32)
#define UNR   6

// out layout: [0,NB) symbolic | [NB,2NB) imm | [2NB,3NB) next | [3NB,..) nsc BxSN

__global__ __launch_bounds__(NTHREADS) void gdvpn_kernel(
    const float* __restrict__ obs,
    const float* __restrict__ ac,
    const float* __restrict__ W1,
    const float* __restrict__ W2,
    const float* __restrict__ W3,
    const float* __restrict__ b3,
    float* __restrict__ out)
{
    // sh[w][5*j+s] = ac[b, j, j+D[s]] or 0; D = {-9,-1,0,+1,+9}
    __shared__ float sh[BPB][SN * 5];
    __shared__ float sh_nsc[BPB][SN];

    const int w    = threadIdx.x >> 5;
    const int lane = threadIdx.x & 31;
    const int b    = blockIdx.x * BPB + w;
    const int sbase = b * SS;

    // pre-zero staging (covers grid-invalid neighbor slots)
    #pragma unroll
    for (int q = lane; q < SN * 5; q += 32) sh[w][q] = 0.0f;
    __syncwarp();

    // ---- Phase 1: per row j, load the 1-2 128B LINES spanning the valid
    // points as warp-wide coalesced loads (L0/L1 warp-uniform). Line set is
    // byte-identical to the scalar-gather floor; wavefronts drop ~2.8x.
    #pragma unroll
    for (int chunk = 0; chunk < (SN + UNR - 1) / UNR; ++chunk) {
        float v0[UNR], v1[UNR];
        int   l0[UNR], l1[UNR];
        const int jbase = chunk * UNR;

        #pragma unroll
        for (int u = 0; u < UNR; ++u) {
            const int j = jbase + u;
            if (j < SN) {
                const int c = j % 9;
                // first/last VALID offset -> exact minimal line span
                const int dF = (j >= 9) ? -9 : ((c > 0) ? -1 : 0);
                const int dL = (j < SN - 9) ? 9 : ((c < 8) ? 1 : 0);
                int L0 = (sbase + 82 * j + dF) >> 5;
                int L1 = (sbase + 82 * j + dL) >> 5;
                if (L0 < 0) L0 = 0;
                if (L1 > MAXLINE) L1 = MAXLINE;
                l0[u] = L0; l1[u] = L1;
                v0[u] = __ldg(ac + (L0 << 5) + lane);
                if (L1 != L0) v1[u] = __ldg(ac + (L1 << 5) + lane);
                else          v1[u] = v0[u];
            }
        }
        #pragma unroll
        for (int u = 0; u < UNR; ++u) {
            const int j = jbase + u;
            if (j < SN) {
                const int c    = j % 9;
                const int base = sbase + 82 * j;
                #pragma unroll
                for (int s = 0; s < 5; ++s) {
                    const int  d  = (s == 0) ? -9 : (s == 1) ? -1 : (s == 2) ? 0
                                  : (s == 3) ?  1 : 9;
                    const bool ok = (s == 0) ? (j >= 9) : (s == 1) ? (c > 0)
                                  : (s == 2) ? true     : (s == 3) ? (c < 8)
                                  : (j < SN - 9);
                    const int P = base + d;
                    if (ok && (P & 31) == lane) {
                        const int line = P >> 5;
                        sh[w][5 * j + s] = (line == l0[u]) ? v0[u] : v1[u];
                    }
                }
            }
        }
    }
    __syncwarp();

    // ---- Phase 2: nsc + served ----
    float served = 0.0f;
    #pragma unroll
    for (int k = 0; k < 3; ++k) {
        const int t = lane + k * 32;
        if (t < SN) {
            const int c = t % 9;
            float vv = sh[w][5 * t + 2];
            if (t >= 9)      vv += sh[w][5 * (t - 9) + 4];
            if (t < SN - 9)  vv += sh[w][5 * (t + 9) + 0];
            if (c > 0)       vv += sh[w][5 * (t - 1) + 3];
            if (c < 8)       vv += sh[w][5 * (t + 1) + 1];

            sh_nsc[w][t] = vv;
            out[(size_t)3 * NB + (size_t)b * SN + t] = vv;

            const float demand = __ldg(obs + (size_t)b * OBSW + SN + t);
            served += fminf(vv, demand);
        }
    }

    #pragma unroll
    for (int o = 16; o > 0; o >>= 1)
        served += __shfl_down_sync(0xFFFFFFFFu, served, o);
    const float imm = __shfl_sync(0xFFFFFFFFu, served, 0);
    __syncwarp();

    // ---- Phase 3: MLP (W1/W2 L1-resident) ----
    float h1 = 0.0f;
    #pragma unroll
    for (int i = 0; i < SN; ++i)
        h1 = fmaf(sh_nsc[w][i], __ldg(W1 + i * HID + lane), h1);
    h1 = fmaxf(h1, 0.0f);

    float h2 = 0.0f;
    #pragma unroll
    for (int m = 0; m < HID; ++m)
        h2 = fmaf(__shfl_sync(0xFFFFFFFFu, h1, m), __ldg(W2 + m * HID + lane), h2);
    h2 = fmaxf(h2, 0.0f);

    float contrib = h2 * __ldg(W3 + lane);
    #pragma unroll
    for (int o = 16; o > 0; o >>= 1)
        contrib += __shfl_down_sync(0xFFFFFFFFu, contrib, o);

    if (lane == 0) {
        const float nr = contrib + __ldg(b3);
        out[b]          = imm + nr;
        out[NB + b]     = imm;
        out[2 * NB + b] = nr;
    }
}

extern "C" void kernel_launch(void* const* d_in, const int* in_sizes, int n_in,
                              void* d_out, int out_size)
{
    const float* obs = (const float*)d_in[0];
    const float* ac  = (const float*)d_in[1];
    const float* W1  = (const float*)d_in[2];
    const float* W2  = (const float*)d_in[3];
    const float* W3  = (const float*)d_in[4];
    const float* b3  = (const float*)d_in[5];
    float* out = (float*)d_out;

    gdvpn_kernel<<<NB / BPB, NTHREADS>>>(obs, ac, W1, W2, W3, b3, out);
}

// round 8
// speedup vs baseline: 1.6569x; 1.6569x over previous
#include <cuda_runtime.h>
#include <cstdint>

#define NB   16384
#define SN   81
#define SS   6561              // 81*81 floats per slice
#define HID  32
#define OBSW 162
#define TPS  4                 // slices per tile
#define TILE_FLOATS (TPS * SS) // 26244
#define TILE_BYTES  (TILE_FLOATS * 4)  // 104976 (multiple of 16)
#define NTILES (NB / TPS)      // 4096
#define GRID  128
#define TPBK  (NTILES / GRID)  // 32 tiles per block, exact
#define NTHREADS 128           // 4 warps = 4 slices per tile

// out layout: [0,NB) symbolic | [NB,2NB) imm | [2NB,3NB) next | [3NB,..) nsc BxSN

__device__ __forceinline__ uint32_t s2u(const void* p) {
    uint32_t a;
    asm("{ .reg .u64 t; cvta.to.shared.u64 t, %1; cvt.u32.u64 %0, t; }"
        : "=r"(a) : "l"(p));
    return a;
}
__device__ __forceinline__ void mbar_init(uint32_t a, uint32_t cnt) {
    asm volatile("mbarrier.init.shared.b64 [%0], %1;" :: "r"(a), "r"(cnt) : "memory");
}
__device__ __forceinline__ void mbar_expect_tx(uint32_t a, uint32_t bytes) {
    asm volatile("mbarrier.arrive.expect_tx.shared.b64 _, [%0], %1;"
                 :: "r"(a), "r"(bytes) : "memory");
}
__device__ __forceinline__ void mbar_wait(uint32_t a, uint32_t phase) {
    asm volatile(
        "{\n\t.reg .pred p;\n\t"
        "WAITLOOP_%=:\n\t"
        "mbarrier.try_wait.parity.acquire.cta.shared::cta.b64 p, [%0], %1, 0x989680;\n\t"
        "@!p bra WAITLOOP_%=;\n\t}"
        :: "r"(a), "r"(phase) : "memory");
}
__device__ __forceinline__ void tma_bulk_1d(uint32_t dst, const float* src,
                                            uint32_t bytes, uint32_t mbar) {
    asm volatile(
        "cp.async.bulk.shared::cluster.global.mbarrier::complete_tx::bytes "
        "[%0], [%1], %2, [%3];"
        :: "r"(dst), "l"(src), "r"(bytes), "r"(mbar) : "memory");
}

__global__ __launch_bounds__(NTHREADS, 1) void gdvpn_kernel(
    const float* __restrict__ obs,
    const float* __restrict__ ac,
    const float* __restrict__ W1,
    const float* __restrict__ W2,
    const float* __restrict__ W3,
    const float* __restrict__ b3,
    float* __restrict__ out)
{
    extern __shared__ float sm[];
    // layout: sm[0..3] = two 8-byte mbarriers; buffers start at float 4 (16B aligned)
    const uint32_t smb  = s2u(sm);
    const uint32_t mb0  = smb;
    const uint32_t mb1  = smb + 8;
    float* buf = sm + 4;
    const uint32_t buf_u = smb + 16;

    const int tid  = threadIdx.x;
    const int w    = tid >> 5;
    const int lane = tid & 31;
    const int t0   = blockIdx.x * TPBK;   // first tile for this block

    if (tid == 0) {
        mbar_init(mb0, 1);
        mbar_init(mb1, 1);
        asm volatile("fence.proxy.async.shared::cta;" ::: "memory");
    }
    __syncthreads();

    // prologue: fill both buffers
    if (tid == 0) {
        mbar_expect_tx(mb0, TILE_BYTES);
        tma_bulk_1d(buf_u,              ac + (size_t)t0 * TILE_FLOATS,       TILE_BYTES, mb0);
        mbar_expect_tx(mb1, TILE_BYTES);
        tma_bulk_1d(buf_u + TILE_BYTES, ac + (size_t)(t0 + 1) * TILE_FLOATS, TILE_BYTES, mb1);
    }

    for (int it = 0; it < TPBK; ++it) {
        const int s  = it & 1;
        const int ph = (it >> 1) & 1;
        const int b  = (t0 + it) * TPS + w;     // slice this warp handles

        // prefetch demand (independent of TMA data)
        float dem[3];
        #pragma unroll
        for (int k = 0; k < 3; ++k) {
            const int t = lane + 32 * k;
            dem[k] = (t < SN) ? __ldg(obs + (size_t)b * OBSW + SN + t) : 0.0f;
        }

        mbar_wait(s ? mb1 : mb0, ph);

        const float* sf = buf + s * TILE_FLOATS + w * SS;  // dense slice in smem

        // nsc + served straight from the dense slice (no staging, no extraction)
        float v[3];
        float served = 0.0f;
        #pragma unroll
        for (int k = 0; k < 3; ++k) {
            const int t = lane + 32 * k;
            float x = 0.0f;
            if (t < SN) {
                const int c = t % 9;
                const int p = 82 * t;            // flat addr of ac[t, t] in slice
                x = sf[p];
                if (t >= 9)      x += sf[p - 729];
                if (t < SN - 9)  x += sf[p + 729];
                if (c > 0)       x += sf[p - 81];
                if (c < 8)       x += sf[p + 81];
                out[(size_t)3 * NB + (size_t)b * SN + t] = x;
                served += fminf(x, dem[k]);
            }
            v[k] = x;
        }

        #pragma unroll
        for (int o = 16; o > 0; o >>= 1)
            served += __shfl_down_sync(0xFFFFFFFFu, served, o);
        const float imm = __shfl_sync(0xFFFFFFFFu, served, 0);

        // MLP: nsc broadcast from registers via shuffle
        float h1 = 0.0f;
        #pragma unroll
        for (int i = 0; i < SN; ++i) {
            const float hm = __shfl_sync(0xFFFFFFFFu, v[i >> 5], i & 31);
            h1 = fmaf(hm, __ldg(W1 + i * HID + lane), h1);
        }
        h1 = fmaxf(h1, 0.0f);

        float h2 = 0.0f;
        #pragma unroll
        for (int m = 0; m < HID; ++m)
            h2 = fmaf(__shfl_sync(0xFFFFFFFFu, h1, m), __ldg(W2 + m * HID + lane), h2);
        h2 = fmaxf(h2, 0.0f);

        float contrib = h2 * __ldg(W3 + lane);
        #pragma unroll
        for (int o = 16; o > 0; o >>= 1)
            contrib += __shfl_down_sync(0xFFFFFFFFu, contrib, o);

        if (lane == 0) {
            const float nr = contrib + __ldg(b3);
            out[b]          = imm + nr;
            out[NB + b]     = imm;
            out[2 * NB + b] = nr;
        }

        // all warps done with buffer s -> refill it with tile it+2
        __syncthreads();
        if (tid == 0 && it + 2 < TPBK) {
            const uint32_t mb = s ? mb1 : mb0;
            mbar_expect_tx(mb, TILE_BYTES);
            tma_bulk_1d(buf_u + s * TILE_BYTES,
                        ac + (size_t)(t0 + it + 2) * TILE_FLOATS, TILE_BYTES, mb);
        }
    }
}

extern "C" void kernel_launch(void* const* d_in, const int* in_sizes, int n_in,
                              void* d_out, int out_size)
{
    const float* obs = (const float*)d_in[0];
    const float* ac  = (const float*)d_in[1];
    const float* W1  = (const float*)d_in[2];
    const float* W2  = (const float*)d_in[3];
    const float* W3  = (const float*)d_in[4];
    const float* b3  = (const float*)d_in[5];
    float* out = (float*)d_out;

    const int smem_bytes = 16 + 2 * TILE_BYTES;   // 209,968 B
    cudaFuncSetAttribute(gdvpn_kernel,
                         cudaFuncAttributeMaxDynamicSharedMemorySize, smem_bytes);
    gdvpn_kernel<<<GRID, NTHREADS, smem_bytes>>>(obs, ac, W1, W2, W3, b3, out);
}